// round 14
// baseline (speedup 1.0000x reference)
#include <cuda_runtime.h>
#include <cstdint>

#define B_    64
#define T_    512
#define H_    8
#define D_    32
#define C_    256
#define M_    (B_*T_)
#define NTOT  24576
#define QKV_ELEMS (NTOT*C_)

__device__ float g_qkv[3 * QKV_ELEMS];   // q,k,v each [token][256] (per DISTINCT token)
__device__ float g_y[M_ * C_];           // attention out per packed slot (tf32-rounded)
__device__ float g_xr[NTOT * C_];        // tf32-rounded x
__device__ float g_wr[4 * C_ * C_];      // tf32-rounded Wq,Wk,Wv,Wp

// ---------------- helpers ----------------------------------------------------
__device__ __forceinline__ uint32_t f2tf32(float f) {
    uint32_t u; asm("cvt.rna.tf32.f32 %0, %1;" : "=r"(u) : "f"(f)); return u;
}
__device__ __forceinline__ float rtf(float f) { return __uint_as_float(f2tf32(f)); }
__device__ __forceinline__ float ex2f(float x) {
    float y; asm("ex2.approx.f32 %0, %1;" : "=f"(y) : "f"(x)); return y;
}
__device__ __forceinline__ void mma8(float* d, const uint32_t* a, uint32_t b0, uint32_t b1) {
    asm volatile(
        "mma.sync.aligned.m16n8k8.row.col.f32.tf32.tf32.f32 "
        "{%0,%1,%2,%3},{%4,%5,%6,%7},{%8,%9},{%0,%1,%2,%3};"
        : "+f"(d[0]), "+f"(d[1]), "+f"(d[2]), "+f"(d[3])
        : "r"(a[0]), "r"(a[1]), "r"(a[2]), "r"(a[3]), "r"(b0), "r"(b1));
}
__device__ __forceinline__ uint32_t smem_u32(const void* p) {
    uint32_t a;
    asm("{ .reg .u64 t; cvta.to.shared.u64 t, %1; cvt.u32.u64 %0, t; }" : "=r"(a) : "l"(p));
    return a;
}
#define CP16(dst, src)  asm volatile("cp.async.cg.shared.global [%0], [%1], 16;" :: "r"(dst), "l"(src))
#define CP_COMMIT()     asm volatile("cp.async.commit_group;" ::: "memory")
#define CP_WAIT1()      asm volatile("cp.async.wait_group 1;" ::: "memory")
#define CP_WAIT0()      asm volatile("cp.async.wait_group 0;" ::: "memory")

// ---------------------------------------------------------------------------
// Pre-rounding pass
// ---------------------------------------------------------------------------
__global__ __launch_bounds__(256) void round_inputs(
    const float* __restrict__ x,
    const float* __restrict__ Wq, const float* __restrict__ Wk,
    const float* __restrict__ Wv, const float* __restrict__ Wp)
{
    const int NX4 = (NTOT * C_) / 4;
    const int NW4 = (C_ * C_) / 4;
    for (int idx = blockIdx.x * 256 + threadIdx.x; idx < NX4 + 4 * NW4;
         idx += gridDim.x * 256) {
        float4 v; float* dst;
        if (idx < NX4) {
            v = ((const float4*)x)[idx];
            dst = g_xr + (size_t)idx * 4;
        } else {
            int w = idx - NX4, z = w / NW4, o = w - z * NW4;
            const float* src = (z == 0) ? Wq : (z == 1) ? Wk : (z == 2) ? Wv : Wp;
            v = ((const float4*)src)[o];
            dst = g_wr + (size_t)z * 65536 + (size_t)o * 4;
        }
        dst[0] = rtf(v.x); dst[1] = rtf(v.y); dst[2] = rtf(v.z); dst[3] = rtf(v.w);
    }
}

// ---------------------------------------------------------------------------
// tf32 GEMM: 128 thr, 4 warps, 64x64 warp tiles, 3-stage cp.async pipeline,
// ONE __syncthreads per chunk. Stride 36 (3 bufs x 2 ops = 110.6KB, 2 CTA/SM).
// ---------------------------------------------------------------------------
#define GSM_STRIDE 36
#define GSM_BUF (128 * GSM_STRIDE)
#define GEMM_SMEM (6 * GSM_BUF * 4)     // 110592 bytes

__device__ __forceinline__ void gemm_tc_core(
    const float* __restrict__ A, const int* __restrict__ gidx,
    const float* __restrict__ W, const float* __restrict__ bias,
    float* __restrict__ outp, int m0, int n0, uint32_t* smg)
{
    const uint32_t sbase = smem_u32(smg);
    const int tid = threadIdx.x;
    const int rb = tid >> 3, kq = tid & 7;

    const float* asrc[8];
#pragma unroll
    for (int l = 0; l < 8; l++) {
        int row = m0 + rb + 16 * l;
        if (gidx) row = gidx[row];
        asrc[l] = A + (size_t)row * 256 + kq * 4;
    }
    const float* wbase = W + (size_t)(n0 + rb) * 256 + kq * 4;
    const uint32_t adst0 = sbase + (rb * GSM_STRIDE + kq * 4) * 4;
    const uint32_t wdst0 = adst0 + 3 * GSM_BUF * 4;

    auto stage = [&](int ch, int buf) {
        const int kof = ch * 32;
        const uint32_t bof = buf * GSM_BUF * 4;
#pragma unroll
        for (int l = 0; l < 8; l++)
            CP16(adst0 + bof + l * (16 * GSM_STRIDE * 4), asrc[l] + kof);
#pragma unroll
        for (int l = 0; l < 8; l++)
            CP16(wdst0 + bof + l * (16 * GSM_STRIDE * 4), wbase + kof + l * 4096);
    };

    const int warp = tid >> 5, lane = tid & 31;
    const int g = lane >> 2, c = lane & 3;
    const int wm = warp >> 1, wn = warp & 1;
    const int mb = wm * 64, nb = wn * 64;

    float acc[4][8][4];
#pragma unroll
    for (int mi = 0; mi < 4; mi++)
#pragma unroll
        for (int ni = 0; ni < 8; ni++)
#pragma unroll
            for (int t = 0; t < 4; t++) acc[mi][ni][t] = 0.f;

    stage(0, 0); CP_COMMIT();
    stage(1, 1); CP_COMMIT();

    for (int ch = 0; ch < 8; ch++) {
        if (ch < 7) CP_WAIT1(); else CP_WAIT0();
        __syncthreads();                         // single sync per chunk

        const int buf = ch % 3;
        const uint32_t* Ab = smg + buf * GSM_BUF;
        const uint32_t* Wb = smg + 3 * GSM_BUF + buf * GSM_BUF;
#pragma unroll
        for (int kt = 0; kt < 4; kt++) {
            const int kc = kt * 8 + c * 2;
            uint32_t af[4][4];
#pragma unroll
            for (int mi = 0; mi < 4; mi++) {
                const int r = mb + mi * 16 + g;
                uint2 a0 = *(const uint2*)&Ab[r * GSM_STRIDE + kc];
                uint2 a1 = *(const uint2*)&Ab[(r + 8) * GSM_STRIDE + kc];
                af[mi][0] = a0.x; af[mi][1] = a1.x;
                af[mi][2] = a0.y; af[mi][3] = a1.y;
            }
            uint2 bf[8];
#pragma unroll
            for (int ni = 0; ni < 8; ni++)
                bf[ni] = *(const uint2*)&Wb[(nb + ni * 8 + g) * GSM_STRIDE + kc];
#pragma unroll
            for (int mi = 0; mi < 4; mi++)
#pragma unroll
                for (int ni = 0; ni < 8; ni++)
                    mma8(acc[mi][ni], af[mi], bf[ni].x, bf[ni].y);
        }
        if (ch < 6) { stage(ch + 2, (ch + 2) % 3); CP_COMMIT(); }
    }

    float2 bz[8];
#pragma unroll
    for (int ni = 0; ni < 8; ni++)
        bz[ni] = *(const float2*)&bias[n0 + nb + ni * 8 + 2 * c];

#pragma unroll
    for (int mi = 0; mi < 4; mi++) {
        const int mA = m0 + mb + mi * 16 + g;
        const int mB = mA + 8;
#pragma unroll
        for (int ni = 0; ni < 8; ni++) {
            const int n = n0 + nb + ni * 8 + 2 * c;
            float2 v0 = make_float2(acc[mi][ni][0] + bz[ni].x, acc[mi][ni][1] + bz[ni].y);
            float2 v1 = make_float2(acc[mi][ni][2] + bz[ni].x, acc[mi][ni][3] + bz[ni].y);
            *(float2*)&outp[(size_t)mA * 256 + n] = v0;
            *(float2*)&outp[(size_t)mB * 256 + n] = v1;
        }
    }
}

__global__ __launch_bounds__(128, 2) void gemm_qkv_tc(
    const float* __restrict__ bq, const float* __restrict__ bk, const float* __restrict__ bv)
{
    extern __shared__ uint32_t smg[];
    const int z = blockIdx.z;
    const float* bi = (z == 0) ? bq : (z == 1 ? bk : bv);
    gemm_tc_core(g_xr, nullptr, g_wr + (size_t)z * 65536, bi,
                 g_qkv + (size_t)z * QKV_ELEMS, blockIdx.x * 128, blockIdx.y * 128, smg);
}

__global__ __launch_bounds__(128, 2) void gemm_proj_tc(
    const int* __restrict__ pinv, const float* __restrict__ bp, float* __restrict__ out)
{
    extern __shared__ uint32_t smg[];
    gemm_tc_core(g_y, pinv, g_wr + 3 * 65536, bp, out,
                 blockIdx.x * 128, blockIdx.y * 128, smg);
}

// ---------------------------------------------------------------------------
// Attention (round-13 structure) + permuted per-warp P buffer (round-7 proven):
// PV A-fragments via uint2 loads. Ks [512][40], Vs [512][36], P [32][68].
// ---------------------------------------------------------------------------
#define KS_OFF 0
#define VS_OFF (512*40)
#define PS_OFF (VS_OFF + 512*36)
#define SEG_OFF (PS_OFF + 8*(32*68))
#define ATTN_SMEM ((SEG_OFF + 512) * 4)    // 227328 bytes

__global__ __launch_bounds__(256, 1) void attn_kernel(
    const int* __restrict__ pbatch, const int* __restrict__ pidx)
{
    extern __shared__ uint32_t sm[];
    uint32_t* Ks = sm + KS_OFF;
    uint32_t* Vs = sm + VS_OFF;
    uint32_t* Ps = sm + PS_OFF;
    int*      seg = (int*)(sm + SEG_OFF);

    const int h = blockIdx.x, b = blockIdx.y;
    const int tid = threadIdx.x;

#pragma unroll
    for (int it = 0; it < 16; it++) {
        int idx = tid + it * 256;            // 0..4095
        int j = idx >> 3, sub = idx & 7;
        int tok = pidx[(b << 9) + j];
        const float* base = g_qkv + (size_t)tok * 256 + h * 32;
        int gq = sub >> 1, ph2 = sub & 1;
        const float* kr = base + QKV_ELEMS + gq * 8 + 2 * ph2;
        float2 lo = *(const float2*)kr;
        float2 hi = *(const float2*)(kr + 4);
        uint4 kv = make_uint4(f2tf32(lo.x), f2tf32(hi.x), f2tf32(lo.y), f2tf32(hi.y));
        *(uint4*)&Ks[j * 40 + gq * 8 + 4 * ph2] = kv;
        float4 vv = *(const float4*)(base + 2 * (size_t)QKV_ELEMS + sub * 4);
        uint4 v = make_uint4(f2tf32(vv.x), f2tf32(vv.y), f2tf32(vv.z), f2tf32(vv.w));
        *(uint4*)&Vs[j * 36 + sub * 4] = v;
    }
    for (int i = tid; i < 512; i += 256) seg[i] = pbatch[b * 512 + i];
    __syncthreads();

    const int warp = tid >> 5, lane = tid & 31;
    const int g = lane >> 2, c = lane & 3;
    uint32_t* Pw = Ps + warp * (32 * 68);
    const float scale = 0.17677669529663688f * 1.4426950408889634f;
    // permuted positions within each 8-wide j-group: pos(jw) = (jw&3)*2 + (jw>>2)
    const int jw0 = 2 * c, jw1 = 2 * c + 1;
    const int pos0 = (jw0 & 3) * 2 + (jw0 >> 2);
    const int pos1 = (jw1 & 3) * 2 + (jw1 >> 2);

    for (int grp = 0; grp < 2; grp++) {
        const int q0 = warp * 64 + grp * 32;
        int rr[2][2]; int sq[2][2];
        uint32_t aq[2][4][4];
#pragma unroll
        for (int t = 0; t < 2; t++) {
            rr[t][0] = q0 + t * 16 + g;
            rr[t][1] = rr[t][0] + 8;
            sq[t][0] = seg[rr[t][0]];
            sq[t][1] = seg[rr[t][1]];
            const float* Q0 = g_qkv + (size_t)pidx[(b << 9) + rr[t][0]] * 256 + h * 32;
            const float* Q1 = g_qkv + (size_t)pidx[(b << 9) + rr[t][1]] * 256 + h * 32;
#pragma unroll
            for (int kt = 0; kt < 4; kt++) {
                aq[t][kt][0] = f2tf32(Q0[kt*8 + c] * scale);
                aq[t][kt][1] = f2tf32(Q1[kt*8 + c] * scale);
                aq[t][kt][2] = f2tf32(Q0[kt*8 + c + 4] * scale);
                aq[t][kt][3] = f2tf32(Q1[kt*8 + c + 4] * scale);
            }
        }

        float l[2][2] = {{0.f, 0.f}, {0.f, 0.f}};
        float y[2][4][4];
#pragma unroll
        for (int t = 0; t < 2; t++)
#pragma unroll
            for (int n = 0; n < 4; n++)
#pragma unroll
                for (int r = 0; r < 4; r++) y[t][n][r] = 0.f;

        for (int ch = 0; ch < 4; ch++) {
            const int j0 = ch * 128;
            float s[2][16][4];
#pragma unroll
            for (int nt = 0; nt < 16; nt++) {
                s[0][nt][0] = s[0][nt][1] = s[0][nt][2] = s[0][nt][3] = 0.f;
                s[1][nt][0] = s[1][nt][1] = s[1][nt][2] = s[1][nt][3] = 0.f;
                const int jb = (j0 + nt*8 + g) * 40;
#pragma unroll
                for (int kt = 0; kt < 4; kt++) {
                    uint2 kk = *(const uint2*)&Ks[jb + kt*8 + c*2];
                    mma8(s[0][nt], aq[0][kt], kk.x, kk.y);
                    mma8(s[1][nt], aq[1][kt], kk.x, kk.y);
                }
            }
#pragma unroll
            for (int nt = 0; nt < 16; nt++) {
                int2 sp = *(const int2*)&seg[j0 + nt*8 + 2*c];
#pragma unroll
                for (int t = 0; t < 2; t++) {
                    float p0 = ex2f((sp.x == sq[t][0]) ? -72.f : s[t][nt][0]);
                    float p1 = ex2f((sp.y == sq[t][0]) ? -72.f : s[t][nt][1]);
                    float p2 = ex2f((sp.x == sq[t][1]) ? -72.f : s[t][nt][2]);
                    float p3 = ex2f((sp.y == sq[t][1]) ? -72.f : s[t][nt][3]);
                    s[t][nt][0] = p0; s[t][nt][1] = p1;
                    s[t][nt][2] = p2; s[t][nt][3] = p3;
                    l[t][0] += p0 + p1; l[t][1] += p2 + p3;
                }
            }

#pragma unroll
            for (int hf = 0; hf < 2; hf++) {
                __syncwarp();
#pragma unroll
                for (int nt2 = 0; nt2 < 8; nt2++) {
                    const int nt = hf * 8 + nt2;
#pragma unroll
                    for (int t = 0; t < 2; t++) {
                        Pw[(t*16 + g)*68     + nt2*8 + pos0] = f2tf32(s[t][nt][0]);
                        Pw[(t*16 + g)*68     + nt2*8 + pos1] = f2tf32(s[t][nt][1]);
                        Pw[(t*16 + g + 8)*68 + nt2*8 + pos0] = f2tf32(s[t][nt][2]);
                        Pw[(t*16 + g + 8)*68 + nt2*8 + pos1] = f2tf32(s[t][nt][3]);
                    }
                }
                __syncwarp();
                const int jh = j0 + hf * 64;
#pragma unroll
                for (int kt2 = 0; kt2 < 8; kt2++) {
                    uint2 u00 = *(const uint2*)&Pw[g*68        + kt2*8 + c*2];
                    uint2 u01 = *(const uint2*)&Pw[(g+8)*68    + kt2*8 + c*2];
                    uint2 u10 = *(const uint2*)&Pw[(16+g)*68   + kt2*8 + c*2];
                    uint2 u11 = *(const uint2*)&Pw[(24+g)*68   + kt2*8 + c*2];
                    uint32_t ap0[4] = {u00.x, u01.x, u00.y, u01.y};
                    uint32_t ap1[4] = {u10.x, u11.x, u10.y, u11.y};
                    const int vb0 = (jh + kt2*8 + c) * 36 + g;
                    const int vb1 = (jh + kt2*8 + c + 4) * 36 + g;
#pragma unroll
                    for (int nt2 = 0; nt2 < 4; nt2++) {
                        uint32_t v0 = Vs[vb0 + nt2*8], v1 = Vs[vb1 + nt2*8];
                        mma8(y[0][nt2], ap0, v0, v1);
                        mma8(y[1][nt2], ap1, v0, v1);
                    }
                }
            }
        }

#pragma unroll
        for (int t = 0; t < 2; t++) {
            float l0 = l[t][0], l1 = l[t][1];
            l0 += __shfl_xor_sync(0xffffffffu, l0, 1);
            l0 += __shfl_xor_sync(0xffffffffu, l0, 2);
            l1 += __shfl_xor_sync(0xffffffffu, l1, 1);
            l1 += __shfl_xor_sync(0xffffffffu, l1, 2);
            const float inv0 = 1.0f / l0, inv1 = 1.0f / l1;

            float* O0 = g_y + (size_t)(b * 512 + rr[t][0]) * 256 + h * 32;
            float* O1 = g_y + (size_t)(b * 512 + rr[t][1]) * 256 + h * 32;
#pragma unroll
            for (int nt2 = 0; nt2 < 4; nt2++) {
                float2 v0 = make_float2(rtf(y[t][nt2][0] * inv0), rtf(y[t][nt2][1] * inv0));
                float2 v1 = make_float2(rtf(y[t][nt2][2] * inv1), rtf(y[t][nt2][3] * inv1));
                *(float2*)&O0[nt2*8 + 2*c] = v0;
                *(float2*)&O1[nt2*8 + 2*c] = v1;
            }
        }
    }
}

// ---------------------------------------------------------------------------

extern "C" void kernel_launch(void* const* d_in, const int* in_sizes, int n_in,
                              void* d_out, int out_size)
{
    const float* x    = (const float*)d_in[0];
    const float* Wq   = (const float*)d_in[1];
    const float* bq   = (const float*)d_in[2];
    const float* Wk   = (const float*)d_in[3];
    const float* bk   = (const float*)d_in[4];
    const float* Wv   = (const float*)d_in[5];
    const float* bv   = (const float*)d_in[6];
    const float* Wp   = (const float*)d_in[7];
    const float* bp   = (const float*)d_in[8];
    const int* pidx   = (const int*)d_in[9];
    const int* pbatch = (const int*)d_in[10];
    const int* pinv   = (const int*)d_in[11];
    float* out = (float*)d_out;

    cudaFuncSetAttribute(gemm_qkv_tc,  cudaFuncAttributeMaxDynamicSharedMemorySize, GEMM_SMEM);
    cudaFuncSetAttribute(gemm_proj_tc, cudaFuncAttributeMaxDynamicSharedMemorySize, GEMM_SMEM);
    cudaFuncSetAttribute(attn_kernel,  cudaFuncAttributeMaxDynamicSharedMemorySize, ATTN_SMEM);

    round_inputs<<<1024, 256>>>(x, Wq, Wk, Wv, Wp);
    gemm_qkv_tc<<<dim3(NTOT / 128, 2, 3), 128, GEMM_SMEM>>>(bq, bk, bv);
    attn_kernel<<<dim3(H_, B_), 256, ATTN_SMEM>>>(pbatch, pidx);
    gemm_proj_tc<<<dim3(NTOT / 128, 2), 128, GEMM_SMEM>>>(pinv, bp, out);
}

// round 15
// speedup vs baseline: 1.0967x; 1.0967x over previous
#include <cuda_runtime.h>
#include <cstdint>

#define B_    64
#define T_    512
#define H_    8
#define D_    32
#define C_    256
#define M_    (B_*T_)
#define NTOT  24576
#define QKV_ELEMS (NTOT*C_)

__device__ float g_qkv[3 * QKV_ELEMS];   // q,k,v each [token][256] (per DISTINCT token)
__device__ float g_y[M_ * C_];           // attention out per packed slot (tf32-rounded)
__device__ float g_xr[NTOT * C_];        // tf32-rounded x
__device__ float g_wr[4 * C_ * C_];      // tf32-rounded Wq,Wk,Wv,Wp

// ---------------- helpers ----------------------------------------------------
__device__ __forceinline__ uint32_t f2tf32(float f) {
    uint32_t u; asm("cvt.rna.tf32.f32 %0, %1;" : "=r"(u) : "f"(f)); return u;
}
__device__ __forceinline__ float rtf(float f) { return __uint_as_float(f2tf32(f)); }
__device__ __forceinline__ float ex2f(float x) {
    float y; asm("ex2.approx.f32 %0, %1;" : "=f"(y) : "f"(x)); return y;
}
__device__ __forceinline__ void mma8(float* d, const uint32_t* a, uint32_t b0, uint32_t b1) {
    asm volatile(
        "mma.sync.aligned.m16n8k8.row.col.f32.tf32.tf32.f32 "
        "{%0,%1,%2,%3},{%4,%5,%6,%7},{%8,%9},{%0,%1,%2,%3};"
        : "+f"(d[0]), "+f"(d[1]), "+f"(d[2]), "+f"(d[3])
        : "r"(a[0]), "r"(a[1]), "r"(a[2]), "r"(a[3]), "r"(b0), "r"(b1));
}
__device__ __forceinline__ uint32_t smem_u32(const void* p) {
    uint32_t a;
    asm("{ .reg .u64 t; cvta.to.shared.u64 t, %1; cvt.u32.u64 %0, t; }" : "=r"(a) : "l"(p));
    return a;
}
#define CP16(dst, src)  asm volatile("cp.async.cg.shared.global [%0], [%1], 16;" :: "r"(dst), "l"(src))
#define CP_COMMIT()     asm volatile("cp.async.commit_group;" ::: "memory")
#define CP_WAIT1()      asm volatile("cp.async.wait_group 1;" ::: "memory")

// ---------------------------------------------------------------------------
// Pre-rounding pass
// ---------------------------------------------------------------------------
__global__ __launch_bounds__(256) void round_inputs(
    const float* __restrict__ x,
    const float* __restrict__ Wq, const float* __restrict__ Wk,
    const float* __restrict__ Wv, const float* __restrict__ Wp)
{
    const int NX4 = (NTOT * C_) / 4;
    const int NW4 = (C_ * C_) / 4;
    for (int idx = blockIdx.x * 256 + threadIdx.x; idx < NX4 + 4 * NW4;
         idx += gridDim.x * 256) {
        float4 v; float* dst;
        if (idx < NX4) {
            v = ((const float4*)x)[idx];
            dst = g_xr + (size_t)idx * 4;
        } else {
            int w = idx - NX4, z = w / NW4, o = w - z * NW4;
            const float* src = (z == 0) ? Wq : (z == 1) ? Wk : (z == 2) ? Wv : Wp;
            v = ((const float4*)src)[o];
            dst = g_wr + (size_t)z * 65536 + (size_t)o * 4;
        }
        dst[0] = rtf(v.x); dst[1] = rtf(v.y); dst[2] = rtf(v.z); dst[3] = rtf(v.w);
    }
}

// ---------------------------------------------------------------------------
// tf32 GEMM (round-13 proven: stride 40, 2-stage cp.async)
// ---------------------------------------------------------------------------
#define GSM_STRIDE 40
#define GSM_BUF (128 * GSM_STRIDE)
#define GEMM_SMEM (4 * GSM_BUF * 4)     // 81920 bytes

__device__ __forceinline__ void gemm_tc_core(
    const float* __restrict__ A, const int* __restrict__ gidx,
    const float* __restrict__ W, const float* __restrict__ bias,
    float* __restrict__ outp, int m0, int n0, uint32_t* smg)
{
    const uint32_t sbase = smem_u32(smg);
    const int tid = threadIdx.x;
    const int rb = tid >> 3, kq = tid & 7;

    const float* asrc[8];
#pragma unroll
    for (int l = 0; l < 8; l++) {
        int row = m0 + rb + 16 * l;
        if (gidx) row = gidx[row];
        asrc[l] = A + (size_t)row * 256 + kq * 4;
    }
    const float* wbase = W + (size_t)(n0 + rb) * 256 + kq * 4;
    const uint32_t adst0 = sbase + (rb * GSM_STRIDE + kq * 4) * 4;
    const uint32_t wdst0 = adst0 + 2 * GSM_BUF * 4;

    auto stage = [&](int ch, int buf) {
        const int kof = ch * 32;
        const uint32_t bof = buf * GSM_BUF * 4;
#pragma unroll
        for (int l = 0; l < 8; l++)
            CP16(adst0 + bof + l * (16 * GSM_STRIDE * 4), asrc[l] + kof);
#pragma unroll
        for (int l = 0; l < 8; l++)
            CP16(wdst0 + bof + l * (16 * GSM_STRIDE * 4), wbase + kof + l * 4096);
    };

    const int warp = tid >> 5, lane = tid & 31;
    const int g = lane >> 2, c = lane & 3;
    const int wm = warp >> 1, wn = warp & 1;
    const int mb = wm * 64, nb = wn * 64;

    float acc[4][8][4];
#pragma unroll
    for (int mi = 0; mi < 4; mi++)
#pragma unroll
        for (int ni = 0; ni < 8; ni++)
#pragma unroll
            for (int t = 0; t < 4; t++) acc[mi][ni][t] = 0.f;

    stage(0, 0); CP_COMMIT();
    stage(1, 1); CP_COMMIT();
    CP_WAIT1(); __syncthreads();

    for (int ch = 0; ch < 8; ch++) {
        const uint32_t* Ab = smg + (ch & 1) * GSM_BUF;
        const uint32_t* Wb = smg + 2 * GSM_BUF + (ch & 1) * GSM_BUF;
#pragma unroll
        for (int kt = 0; kt < 4; kt++) {
            const int kc = kt * 8 + c * 2;
            uint32_t af[4][4];
#pragma unroll
            for (int mi = 0; mi < 4; mi++) {
                const int r = mb + mi * 16 + g;
                uint2 a0 = *(const uint2*)&Ab[r * GSM_STRIDE + kc];
                uint2 a1 = *(const uint2*)&Ab[(r + 8) * GSM_STRIDE + kc];
                af[mi][0] = a0.x; af[mi][1] = a1.x;
                af[mi][2] = a0.y; af[mi][3] = a1.y;
            }
            uint2 bf[8];
#pragma unroll
            for (int ni = 0; ni < 8; ni++)
                bf[ni] = *(const uint2*)&Wb[(nb + ni * 8 + g) * GSM_STRIDE + kc];
#pragma unroll
            for (int mi = 0; mi < 4; mi++)
#pragma unroll
                for (int ni = 0; ni < 8; ni++)
                    mma8(acc[mi][ni], af[mi], bf[ni].x, bf[ni].y);
        }
        __syncthreads();
        if (ch < 6) { stage(ch + 2, ch & 1); CP_COMMIT(); }
        if (ch < 7) { CP_WAIT1(); __syncthreads(); }
    }

    float2 bz[8];
#pragma unroll
    for (int ni = 0; ni < 8; ni++)
        bz[ni] = *(const float2*)&bias[n0 + nb + ni * 8 + 2 * c];

#pragma unroll
    for (int mi = 0; mi < 4; mi++) {
        const int mA = m0 + mb + mi * 16 + g;
        const int mB = mA + 8;
#pragma unroll
        for (int ni = 0; ni < 8; ni++) {
            const int n = n0 + nb + ni * 8 + 2 * c;
            float2 v0 = make_float2(acc[mi][ni][0] + bz[ni].x, acc[mi][ni][1] + bz[ni].y);
            float2 v1 = make_float2(acc[mi][ni][2] + bz[ni].x, acc[mi][ni][3] + bz[ni].y);
            *(float2*)&outp[(size_t)mA * 256 + n] = v0;
            *(float2*)&outp[(size_t)mB * 256 + n] = v1;
        }
    }
}

__global__ __launch_bounds__(128, 2) void gemm_qkv_tc(
    const float* __restrict__ bq, const float* __restrict__ bk, const float* __restrict__ bv)
{
    extern __shared__ uint32_t smg[];
    const int z = blockIdx.z;
    const float* bi = (z == 0) ? bq : (z == 1 ? bk : bv);
    gemm_tc_core(g_xr, nullptr, g_wr + (size_t)z * 65536, bi,
                 g_qkv + (size_t)z * QKV_ELEMS, blockIdx.x * 128, blockIdx.y * 128, smg);
}

__global__ __launch_bounds__(128, 2) void gemm_proj_tc(
    const int* __restrict__ pinv, const float* __restrict__ bp, float* __restrict__ out)
{
    extern __shared__ uint32_t smg[];
    gemm_tc_core(g_y, pinv, g_wr + 3 * 65536, bp, out,
                 blockIdx.x * 128, blockIdx.y * 128, smg);
}

// ---------------------------------------------------------------------------
// Attention (round-13 proven math/layouts) split 2x along queries:
// grid (H, B, 2); each CTA stages full K/V but processes 256 queries.
// Ks [512][40] permuted, Vs [512][36], per-warp P [32][68].
// ---------------------------------------------------------------------------
#define KS_OFF 0
#define VS_OFF (512*40)
#define PS_OFF (VS_OFF + 512*36)
#define SEG_OFF (PS_OFF + 8*(32*68))
#define ATTN_SMEM ((SEG_OFF + 512) * 4)    // 227328 bytes

__global__ __launch_bounds__(256, 1) void attn_kernel(
    const int* __restrict__ pbatch, const int* __restrict__ pidx)
{
    extern __shared__ uint32_t sm[];
    uint32_t* Ks = sm + KS_OFF;
    uint32_t* Vs = sm + VS_OFF;
    uint32_t* Ps = sm + PS_OFF;
    int*      seg = (int*)(sm + SEG_OFF);

    const int h = blockIdx.x, b = blockIdx.y;
    const int half = blockIdx.z;
    const int tid = threadIdx.x;

    // K (permuted) + V (identity) staging, rows gathered via pidx
#pragma unroll
    for (int it = 0; it < 16; it++) {
        int idx = tid + it * 256;            // 0..4095
        int j = idx >> 3, sub = idx & 7;
        int tok = pidx[(b << 9) + j];
        const float* base = g_qkv + (size_t)tok * 256 + h * 32;
        int gq = sub >> 1, ph2 = sub & 1;
        const float* kr = base + QKV_ELEMS + gq * 8 + 2 * ph2;
        float2 lo = *(const float2*)kr;
        float2 hi = *(const float2*)(kr + 4);
        uint4 kv = make_uint4(f2tf32(lo.x), f2tf32(hi.x), f2tf32(lo.y), f2tf32(hi.y));
        *(uint4*)&Ks[j * 40 + gq * 8 + 4 * ph2] = kv;
        float4 vv = *(const float4*)(base + 2 * (size_t)QKV_ELEMS + sub * 4);
        uint4 v = make_uint4(f2tf32(vv.x), f2tf32(vv.y), f2tf32(vv.z), f2tf32(vv.w));
        *(uint4*)&Vs[j * 36 + sub * 4] = v;
    }
    for (int i = tid; i < 512; i += 256) seg[i] = pbatch[b * 512 + i];
    __syncthreads();

    const int warp = tid >> 5, lane = tid & 31;
    const int g = lane >> 2, c = lane & 3;
    uint32_t* Pw = Ps + warp * (32 * 68);
    const float scale = 0.17677669529663688f * 1.4426950408889634f;

    // this CTA's 256 queries: warp handles 32 (two 16-q m-tiles, one pass)
    const int q0 = half * 256 + warp * 32;
    int rr[2][2]; int sq[2][2];
    uint32_t aq[2][4][4];
#pragma unroll
    for (int t = 0; t < 2; t++) {
        rr[t][0] = q0 + t * 16 + g;
        rr[t][1] = rr[t][0] + 8;
        sq[t][0] = seg[rr[t][0]];
        sq[t][1] = seg[rr[t][1]];
        const float* Q0 = g_qkv + (size_t)pidx[(b << 9) + rr[t][0]] * 256 + h * 32;
        const float* Q1 = g_qkv + (size_t)pidx[(b << 9) + rr[t][1]] * 256 + h * 32;
#pragma unroll
        for (int kt = 0; kt < 4; kt++) {
            aq[t][kt][0] = f2tf32(Q0[kt*8 + c] * scale);
            aq[t][kt][1] = f2tf32(Q1[kt*8 + c] * scale);
            aq[t][kt][2] = f2tf32(Q0[kt*8 + c + 4] * scale);
            aq[t][kt][3] = f2tf32(Q1[kt*8 + c + 4] * scale);
        }
    }

    float l[2][2] = {{0.f, 0.f}, {0.f, 0.f}};
    float y[2][4][4];
#pragma unroll
    for (int t = 0; t < 2; t++)
#pragma unroll
        for (int n = 0; n < 4; n++)
#pragma unroll
            for (int r = 0; r < 4; r++) y[t][n][r] = 0.f;

    for (int ch = 0; ch < 4; ch++) {
        const int j0 = ch * 128;
        float s[2][16][4];
#pragma unroll
        for (int nt = 0; nt < 16; nt++) {
            s[0][nt][0] = s[0][nt][1] = s[0][nt][2] = s[0][nt][3] = 0.f;
            s[1][nt][0] = s[1][nt][1] = s[1][nt][2] = s[1][nt][3] = 0.f;
            const int jb = (j0 + nt*8 + g) * 40;
#pragma unroll
            for (int kt = 0; kt < 4; kt++) {
                uint2 kk = *(const uint2*)&Ks[jb + kt*8 + c*2];
                mma8(s[0][nt], aq[0][kt], kk.x, kk.y);
                mma8(s[1][nt], aq[1][kt], kk.x, kk.y);
            }
        }
#pragma unroll
        for (int nt = 0; nt < 16; nt++) {
            int2 sp = *(const int2*)&seg[j0 + nt*8 + 2*c];
#pragma unroll
            for (int t = 0; t < 2; t++) {
                float p0 = ex2f((sp.x == sq[t][0]) ? -72.f : s[t][nt][0]);
                float p1 = ex2f((sp.y == sq[t][0]) ? -72.f : s[t][nt][1]);
                float p2 = ex2f((sp.x == sq[t][1]) ? -72.f : s[t][nt][2]);
                float p3 = ex2f((sp.y == sq[t][1]) ? -72.f : s[t][nt][3]);
                s[t][nt][0] = p0; s[t][nt][1] = p1;
                s[t][nt][2] = p2; s[t][nt][3] = p3;
                l[t][0] += p0 + p1; l[t][1] += p2 + p3;
            }
        }

#pragma unroll
        for (int hf = 0; hf < 2; hf++) {
            __syncwarp();
#pragma unroll
            for (int nt2 = 0; nt2 < 8; nt2++) {
                const int nt = hf * 8 + nt2;
#pragma unroll
                for (int t = 0; t < 2; t++) {
                    Pw[(t*16 + g)*68     + nt2*8 + 2*c    ] = f2tf32(s[t][nt][0]);
                    Pw[(t*16 + g)*68     + nt2*8 + 2*c + 1] = f2tf32(s[t][nt][1]);
                    Pw[(t*16 + g + 8)*68 + nt2*8 + 2*c    ] = f2tf32(s[t][nt][2]);
                    Pw[(t*16 + g + 8)*68 + nt2*8 + 2*c + 1] = f2tf32(s[t][nt][3]);
                }
            }
            __syncwarp();
            const int jh = j0 + hf * 64;
#pragma unroll
            for (int kt2 = 0; kt2 < 8; kt2++) {
                uint32_t ap0[4], ap1[4];
                ap0[0] = Pw[g*68        + kt2*8 + c];
                ap0[1] = Pw[(g+8)*68    + kt2*8 + c];
                ap0[2] = Pw[g*68        + kt2*8 + c + 4];
                ap0[3] = Pw[(g+8)*68    + kt2*8 + c + 4];
                ap1[0] = Pw[(16+g)*68   + kt2*8 + c];
                ap1[1] = Pw[(24+g)*68   + kt2*8 + c];
                ap1[2] = Pw[(16+g)*68   + kt2*8 + c + 4];
                ap1[3] = Pw[(24+g)*68   + kt2*8 + c + 4];
                const int vb0 = (jh + kt2*8 + c) * 36 + g;
                const int vb1 = (jh + kt2*8 + c + 4) * 36 + g;
#pragma unroll
                for (int nt2 = 0; nt2 < 4; nt2++) {
                    uint32_t v0 = Vs[vb0 + nt2*8], v1 = Vs[vb1 + nt2*8];
                    mma8(y[0][nt2], ap0, v0, v1);
                    mma8(y[1][nt2], ap1, v0, v1);
                }
            }
        }
    }

#pragma unroll
    for (int t = 0; t < 2; t++) {
        float l0 = l[t][0], l1 = l[t][1];
        l0 += __shfl_xor_sync(0xffffffffu, l0, 1);
        l0 += __shfl_xor_sync(0xffffffffu, l0, 2);
        l1 += __shfl_xor_sync(0xffffffffu, l1, 1);
        l1 += __shfl_xor_sync(0xffffffffu, l1, 2);
        const float inv0 = 1.0f / l0, inv1 = 1.0f / l1;

        float* O0 = g_y + (size_t)(b * 512 + rr[t][0]) * 256 + h * 32;
        float* O1 = g_y + (size_t)(b * 512 + rr[t][1]) * 256 + h * 32;
#pragma unroll
        for (int nt2 = 0; nt2 < 4; nt2++) {
            float2 v0 = make_float2(rtf(y[t][nt2][0] * inv0), rtf(y[t][nt2][1] * inv0));
            float2 v1 = make_float2(rtf(y[t][nt2][2] * inv1), rtf(y[t][nt2][3] * inv1));
            *(float2*)&O0[nt2*8 + 2*c] = v0;
            *(float2*)&O1[nt2*8 + 2*c] = v1;
        }
    }
}

// ---------------------------------------------------------------------------

extern "C" void kernel_launch(void* const* d_in, const int* in_sizes, int n_in,
                              void* d_out, int out_size)
{
    const float* x    = (const float*)d_in[0];
    const float* Wq   = (const float*)d_in[1];
    const float* bq   = (const float*)d_in[2];
    const float* Wk   = (const float*)d_in[3];
    const float* bk   = (const float*)d_in[4];
    const float* Wv   = (const float*)d_in[5];
    const float* bv   = (const float*)d_in[6];
    const float* Wp   = (const float*)d_in[7];
    const float* bp   = (const float*)d_in[8];
    const int* pidx   = (const int*)d_in[9];
    const int* pbatch = (const int*)d_in[10];
    const int* pinv   = (const int*)d_in[11];
    float* out = (float*)d_out;

    cudaFuncSetAttribute(gemm_qkv_tc,  cudaFuncAttributeMaxDynamicSharedMemorySize, GEMM_SMEM);
    cudaFuncSetAttribute(gemm_proj_tc, cudaFuncAttributeMaxDynamicSharedMemorySize, GEMM_SMEM);
    cudaFuncSetAttribute(attn_kernel,  cudaFuncAttributeMaxDynamicSharedMemorySize, ATTN_SMEM);

    round_inputs<<<1024, 256>>>(x, Wq, Wk, Wv, Wp);
    gemm_qkv_tc<<<dim3(NTOT / 128, 2, 3), 128, GEMM_SMEM>>>(bq, bk, bv);
    attn_kernel<<<dim3(H_, B_, 2), 256, ATTN_SMEM>>>(pbatch, pidx);
    gemm_proj_tc<<<dim3(NTOT / 128, 2), 128, GEMM_SMEM>>>(pinv, bp, out);
}

// round 16
// speedup vs baseline: 1.1158x; 1.0174x over previous
#include <cuda_runtime.h>
#include <cstdint>

#define B_    64
#define T_    512
#define H_    8
#define D_    32
#define C_    256
#define M_    (B_*T_)
#define NTOT  24576
#define QKV_ELEMS (NTOT*C_)

__device__ float g_qkv[3 * QKV_ELEMS];   // q,k,v each [token][256] (per DISTINCT token)
__device__ float g_y[M_ * C_];           // attention out per packed slot (tf32-rounded)
__device__ float g_wr[4 * C_ * C_];      // tf32-rounded Wq,Wk,Wv,Wp

// ---------------- helpers ----------------------------------------------------
__device__ __forceinline__ uint32_t f2tf32(float f) {
    uint32_t u; asm("cvt.rna.tf32.f32 %0, %1;" : "=r"(u) : "f"(f)); return u;
}
__device__ __forceinline__ float rtf(float f) { return __uint_as_float(f2tf32(f)); }
__device__ __forceinline__ float ex2f(float x) {
    float y; asm("ex2.approx.f32 %0, %1;" : "=f"(y) : "f"(x)); return y;
}
__device__ __forceinline__ void mma8(float* d, const uint32_t* a, uint32_t b0, uint32_t b1) {
    asm volatile(
        "mma.sync.aligned.m16n8k8.row.col.f32.tf32.tf32.f32 "
        "{%0,%1,%2,%3},{%4,%5,%6,%7},{%8,%9},{%0,%1,%2,%3};"
        : "+f"(d[0]), "+f"(d[1]), "+f"(d[2]), "+f"(d[3])
        : "r"(a[0]), "r"(a[1]), "r"(a[2]), "r"(a[3]), "r"(b0), "r"(b1));
}
__device__ __forceinline__ uint32_t smem_u32(const void* p) {
    uint32_t a;
    asm("{ .reg .u64 t; cvta.to.shared.u64 t, %1; cvt.u32.u64 %0, t; }" : "=r"(a) : "l"(p));
    return a;
}
#define CP16(dst, src)  asm volatile("cp.async.cg.shared.global [%0], [%1], 16;" :: "r"(dst), "l"(src))
#define CP_COMMIT()     asm volatile("cp.async.commit_group;" ::: "memory")
#define CP_WAIT1()      asm volatile("cp.async.wait_group 1;" ::: "memory")

// ---------------------------------------------------------------------------
// Weight pre-rounding only (1 MB total; x now fed raw to the GEMM, HW truncates)
// ---------------------------------------------------------------------------
__global__ __launch_bounds__(256) void round_weights(
    const float* __restrict__ Wq, const float* __restrict__ Wk,
    const float* __restrict__ Wv, const float* __restrict__ Wp)
{
    const int NW4 = (C_ * C_) / 4;       // 16384
    for (int idx = blockIdx.x * 256 + threadIdx.x; idx < 4 * NW4;
         idx += gridDim.x * 256) {
        int z = idx / NW4, o = idx - z * NW4;
        const float* src = (z == 0) ? Wq : (z == 1) ? Wk : (z == 2) ? Wv : Wp;
        float4 v = ((const float4*)src)[o];
        float* dst = g_wr + (size_t)z * 65536 + (size_t)o * 4;
        dst[0] = rtf(v.x); dst[1] = rtf(v.y); dst[2] = rtf(v.z); dst[3] = rtf(v.w);
    }
}

// ---------------------------------------------------------------------------
// tf32 GEMM (round-13 proven: stride 40, 2-stage cp.async)
// ---------------------------------------------------------------------------
#define GSM_STRIDE 40
#define GSM_BUF (128 * GSM_STRIDE)
#define GEMM_SMEM (4 * GSM_BUF * 4)     // 81920 bytes

__device__ __forceinline__ void gemm_tc_core(
    const float* __restrict__ A, const int* __restrict__ gidx,
    const float* __restrict__ W, const float* __restrict__ bias,
    float* __restrict__ outp, int m0, int n0, uint32_t* smg)
{
    const uint32_t sbase = smem_u32(smg);
    const int tid = threadIdx.x;
    const int rb = tid >> 3, kq = tid & 7;

    const float* asrc[8];
#pragma unroll
    for (int l = 0; l < 8; l++) {
        int row = m0 + rb + 16 * l;
        if (gidx) row = gidx[row];
        asrc[l] = A + (size_t)row * 256 + kq * 4;
    }
    const float* wbase = W + (size_t)(n0 + rb) * 256 + kq * 4;
    const uint32_t adst0 = sbase + (rb * GSM_STRIDE + kq * 4) * 4;
    const uint32_t wdst0 = adst0 + 2 * GSM_BUF * 4;

    auto stage = [&](int ch, int buf) {
        const int kof = ch * 32;
        const uint32_t bof = buf * GSM_BUF * 4;
#pragma unroll
        for (int l = 0; l < 8; l++)
            CP16(adst0 + bof + l * (16 * GSM_STRIDE * 4), asrc[l] + kof);
#pragma unroll
        for (int l = 0; l < 8; l++)
            CP16(wdst0 + bof + l * (16 * GSM_STRIDE * 4), wbase + kof + l * 4096);
    };

    const int warp = tid >> 5, lane = tid & 31;
    const int g = lane >> 2, c = lane & 3;
    const int wm = warp >> 1, wn = warp & 1;
    const int mb = wm * 64, nb = wn * 64;

    float acc[4][8][4];
#pragma unroll
    for (int mi = 0; mi < 4; mi++)
#pragma unroll
        for (int ni = 0; ni < 8; ni++)
#pragma unroll
            for (int t = 0; t < 4; t++) acc[mi][ni][t] = 0.f;

    stage(0, 0); CP_COMMIT();
    stage(1, 1); CP_COMMIT();
    CP_WAIT1(); __syncthreads();

    for (int ch = 0; ch < 8; ch++) {
        const uint32_t* Ab = smg + (ch & 1) * GSM_BUF;
        const uint32_t* Wb = smg + 2 * GSM_BUF + (ch & 1) * GSM_BUF;
#pragma unroll
        for (int kt = 0; kt < 4; kt++) {
            const int kc = kt * 8 + c * 2;
            uint32_t af[4][4];
#pragma unroll
            for (int mi = 0; mi < 4; mi++) {
                const int r = mb + mi * 16 + g;
                uint2 a0 = *(const uint2*)&Ab[r * GSM_STRIDE + kc];
                uint2 a1 = *(const uint2*)&Ab[(r + 8) * GSM_STRIDE + kc];
                af[mi][0] = a0.x; af[mi][1] = a1.x;
                af[mi][2] = a0.y; af[mi][3] = a1.y;
            }
            uint2 bf[8];
#pragma unroll
            for (int ni = 0; ni < 8; ni++)
                bf[ni] = *(const uint2*)&Wb[(nb + ni * 8 + g) * GSM_STRIDE + kc];
#pragma unroll
            for (int mi = 0; mi < 4; mi++)
#pragma unroll
                for (int ni = 0; ni < 8; ni++)
                    mma8(acc[mi][ni], af[mi], bf[ni].x, bf[ni].y);
        }
        __syncthreads();
        if (ch < 6) { stage(ch + 2, ch & 1); CP_COMMIT(); }
        if (ch < 7) { CP_WAIT1(); __syncthreads(); }
    }

    float2 bz[8];
#pragma unroll
    for (int ni = 0; ni < 8; ni++)
        bz[ni] = *(const float2*)&bias[n0 + nb + ni * 8 + 2 * c];

#pragma unroll
    for (int mi = 0; mi < 4; mi++) {
        const int mA = m0 + mb + mi * 16 + g;
        const int mB = mA + 8;
#pragma unroll
        for (int ni = 0; ni < 8; ni++) {
            const int n = n0 + nb + ni * 8 + 2 * c;
            float2 v0 = make_float2(acc[mi][ni][0] + bz[ni].x, acc[mi][ni][1] + bz[ni].y);
            float2 v1 = make_float2(acc[mi][ni][2] + bz[ni].x, acc[mi][ni][3] + bz[ni].y);
            *(float2*)&outp[(size_t)mA * 256 + n] = v0;
            *(float2*)&outp[(size_t)mB * 256 + n] = v1;
        }
    }
}

__global__ __launch_bounds__(128, 2) void gemm_qkv_tc(
    const float* __restrict__ x,
    const float* __restrict__ bq, const float* __restrict__ bk, const float* __restrict__ bv)
{
    extern __shared__ uint32_t smg[];
    const int z = blockIdx.z;
    const float* bi = (z == 0) ? bq : (z == 1 ? bk : bv);
    gemm_tc_core(x, nullptr, g_wr + (size_t)z * 65536, bi,
                 g_qkv + (size_t)z * QKV_ELEMS, blockIdx.x * 128, blockIdx.y * 128, smg);
}

__global__ __launch_bounds__(128, 2) void gemm_proj_tc(
    const int* __restrict__ pinv, const float* __restrict__ bp, float* __restrict__ out)
{
    extern __shared__ uint32_t smg[];
    gemm_tc_core(g_y, pinv, g_wr + 3 * 65536, bp, out,
                 blockIdx.x * 128, blockIdx.y * 128, smg);
}

// ---------------------------------------------------------------------------
// Attention (round-15 proven): grid (H, B, 2), 256 thr, two 16-q m-tiles/warp.
// Ks [512][40] permuted, Vs [512][36], per-warp P [32][68].
// ---------------------------------------------------------------------------
#define KS_OFF 0
#define VS_OFF (512*40)
#define PS_OFF (VS_OFF + 512*36)
#define SEG_OFF (PS_OFF + 8*(32*68))
#define ATTN_SMEM ((SEG_OFF + 512) * 4)    // 227328 bytes

__global__ __launch_bounds__(256, 1) void attn_kernel(
    const int* __restrict__ pbatch, const int* __restrict__ pidx)
{
    extern __shared__ uint32_t sm[];
    uint32_t* Ks = sm + KS_OFF;
    uint32_t* Vs = sm + VS_OFF;
    uint32_t* Ps = sm + PS_OFF;
    int*      seg = (int*)(sm + SEG_OFF);

    const int h = blockIdx.x, b = blockIdx.y;
    const int half = blockIdx.z;
    const int tid = threadIdx.x;

#pragma unroll
    for (int it = 0; it < 16; it++) {
        int idx = tid + it * 256;            // 0..4095
        int j = idx >> 3, sub = idx & 7;
        int tok = pidx[(b << 9) + j];
        const float* base = g_qkv + (size_t)tok * 256 + h * 32;
        int gq = sub >> 1, ph2 = sub & 1;
        const float* kr = base + QKV_ELEMS + gq * 8 + 2 * ph2;
        float2 lo = *(const float2*)kr;
        float2 hi = *(const float2*)(kr + 4);
        uint4 kv = make_uint4(f2tf32(lo.x), f2tf32(hi.x), f2tf32(lo.y), f2tf32(hi.y));
        *(uint4*)&Ks[j * 40 + gq * 8 + 4 * ph2] = kv;
        float4 vv = *(const float4*)(base + 2 * (size_t)QKV_ELEMS + sub * 4);
        uint4 v = make_uint4(f2tf32(vv.x), f2tf32(vv.y), f2tf32(vv.z), f2tf32(vv.w));
        *(uint4*)&Vs[j * 36 + sub * 4] = v;
    }
    for (int i = tid; i < 512; i += 256) seg[i] = pbatch[b * 512 + i];
    __syncthreads();

    const int warp = tid >> 5, lane = tid & 31;
    const int g = lane >> 2, c = lane & 3;
    uint32_t* Pw = Ps + warp * (32 * 68);
    const float scale = 0.17677669529663688f * 1.4426950408889634f;

    const int q0 = half * 256 + warp * 32;
    int rr[2][2]; int sq[2][2];
    uint32_t aq[2][4][4];
#pragma unroll
    for (int t = 0; t < 2; t++) {
        rr[t][0] = q0 + t * 16 + g;
        rr[t][1] = rr[t][0] + 8;
        sq[t][0] = seg[rr[t][0]];
        sq[t][1] = seg[rr[t][1]];
        const float* Q0 = g_qkv + (size_t)pidx[(b << 9) + rr[t][0]] * 256 + h * 32;
        const float* Q1 = g_qkv + (size_t)pidx[(b << 9) + rr[t][1]] * 256 + h * 32;
#pragma unroll
        for (int kt = 0; kt < 4; kt++) {
            aq[t][kt][0] = f2tf32(Q0[kt*8 + c] * scale);
            aq[t][kt][1] = f2tf32(Q1[kt*8 + c] * scale);
            aq[t][kt][2] = f2tf32(Q0[kt*8 + c + 4] * scale);
            aq[t][kt][3] = f2tf32(Q1[kt*8 + c + 4] * scale);
        }
    }

    float l[2][2] = {{0.f, 0.f}, {0.f, 0.f}};
    float y[2][4][4];
#pragma unroll
    for (int t = 0; t < 2; t++)
#pragma unroll
        for (int n = 0; n < 4; n++)
#pragma unroll
            for (int r = 0; r < 4; r++) y[t][n][r] = 0.f;

    for (int ch = 0; ch < 4; ch++) {
        const int j0 = ch * 128;
        float s[2][16][4];
#pragma unroll
        for (int nt = 0; nt < 16; nt++) {
            s[0][nt][0] = s[0][nt][1] = s[0][nt][2] = s[0][nt][3] = 0.f;
            s[1][nt][0] = s[1][nt][1] = s[1][nt][2] = s[1][nt][3] = 0.f;
            const int jb = (j0 + nt*8 + g) * 40;
#pragma unroll
            for (int kt = 0; kt < 4; kt++) {
                uint2 kk = *(const uint2*)&Ks[jb + kt*8 + c*2];
                mma8(s[0][nt], aq[0][kt], kk.x, kk.y);
                mma8(s[1][nt], aq[1][kt], kk.x, kk.y);
            }
        }
#pragma unroll
        for (int nt = 0; nt < 16; nt++) {
            int2 sp = *(const int2*)&seg[j0 + nt*8 + 2*c];
#pragma unroll
            for (int t = 0; t < 2; t++) {
                float p0 = ex2f((sp.x == sq[t][0]) ? -72.f : s[t][nt][0]);
                float p1 = ex2f((sp.y == sq[t][0]) ? -72.f : s[t][nt][1]);
                float p2 = ex2f((sp.x == sq[t][1]) ? -72.f : s[t][nt][2]);
                float p3 = ex2f((sp.y == sq[t][1]) ? -72.f : s[t][nt][3]);
                s[t][nt][0] = p0; s[t][nt][1] = p1;
                s[t][nt][2] = p2; s[t][nt][3] = p3;
                l[t][0] += p0 + p1; l[t][1] += p2 + p3;
            }
        }

#pragma unroll
        for (int hf = 0; hf < 2; hf++) {
            __syncwarp();
#pragma unroll
            for (int nt2 = 0; nt2 < 8; nt2++) {
                const int nt = hf * 8 + nt2;
#pragma unroll
                for (int t = 0; t < 2; t++) {
                    Pw[(t*16 + g)*68     + nt2*8 + 2*c    ] = f2tf32(s[t][nt][0]);
                    Pw[(t*16 + g)*68     + nt2*8 + 2*c + 1] = f2tf32(s[t][nt][1]);
                    Pw[(t*16 + g + 8)*68 + nt2*8 + 2*c    ] = f2tf32(s[t][nt][2]);
                    Pw[(t*16 + g + 8)*68 + nt2*8 + 2*c + 1] = f2tf32(s[t][nt][3]);
                }
            }
            __syncwarp();
            const int jh = j0 + hf * 64;
#pragma unroll
            for (int kt2 = 0; kt2 < 8; kt2++) {
                uint32_t ap0[4], ap1[4];
                ap0[0] = Pw[g*68        + kt2*8 + c];
                ap0[1] = Pw[(g+8)*68    + kt2*8 + c];
                ap0[2] = Pw[g*68        + kt2*8 + c + 4];
                ap0[3] = Pw[(g+8)*68    + kt2*8 + c + 4];
                ap1[0] = Pw[(16+g)*68   + kt2*8 + c];
                ap1[1] = Pw[(24+g)*68   + kt2*8 + c];
                ap1[2] = Pw[(16+g)*68   + kt2*8 + c + 4];
                ap1[3] = Pw[(24+g)*68   + kt2*8 + c + 4];
                const int vb0 = (jh + kt2*8 + c) * 36 + g;
                const int vb1 = (jh + kt2*8 + c + 4) * 36 + g;
#pragma unroll
                for (int nt2 = 0; nt2 < 4; nt2++) {
                    uint32_t v0 = Vs[vb0 + nt2*8], v1 = Vs[vb1 + nt2*8];
                    mma8(y[0][nt2], ap0, v0, v1);
                    mma8(y[1][nt2], ap1, v0, v1);
                }
            }
        }
    }

#pragma unroll
    for (int t = 0; t < 2; t++) {
        float l0 = l[t][0], l1 = l[t][1];
        l0 += __shfl_xor_sync(0xffffffffu, l0, 1);
        l0 += __shfl_xor_sync(0xffffffffu, l0, 2);
        l1 += __shfl_xor_sync(0xffffffffu, l1, 1);
        l1 += __shfl_xor_sync(0xffffffffu, l1, 2);
        const float inv0 = 1.0f / l0, inv1 = 1.0f / l1;

        float* O0 = g_y + (size_t)(b * 512 + rr[t][0]) * 256 + h * 32;
        float* O1 = g_y + (size_t)(b * 512 + rr[t][1]) * 256 + h * 32;
#pragma unroll
        for (int nt2 = 0; nt2 < 4; nt2++) {
            float2 v0 = make_float2(rtf(y[t][nt2][0] * inv0), rtf(y[t][nt2][1] * inv0));
            float2 v1 = make_float2(rtf(y[t][nt2][2] * inv1), rtf(y[t][nt2][3] * inv1));
            *(float2*)&O0[nt2*8 + 2*c] = v0;
            *(float2*)&O1[nt2*8 + 2*c] = v1;
        }
    }
}

// ---------------------------------------------------------------------------

extern "C" void kernel_launch(void* const* d_in, const int* in_sizes, int n_in,
                              void* d_out, int out_size)
{
    const float* x    = (const float*)d_in[0];
    const float* Wq   = (const float*)d_in[1];
    const float* bq   = (const float*)d_in[2];
    const float* Wk   = (const float*)d_in[3];
    const float* bk   = (const float*)d_in[4];
    const float* Wv   = (const float*)d_in[5];
    const float* bv   = (const float*)d_in[6];
    const float* Wp   = (const float*)d_in[7];
    const float* bp   = (const float*)d_in[8];
    const int* pidx   = (const int*)d_in[9];
    const int* pbatch = (const int*)d_in[10];
    const int* pinv   = (const int*)d_in[11];
    float* out = (float*)d_out;

    cudaFuncSetAttribute(gemm_qkv_tc,  cudaFuncAttributeMaxDynamicSharedMemorySize, GEMM_SMEM);
    cudaFuncSetAttribute(gemm_proj_tc, cudaFuncAttributeMaxDynamicSharedMemorySize, GEMM_SMEM);
    cudaFuncSetAttribute(attn_kernel,  cudaFuncAttributeMaxDynamicSharedMemorySize, ATTN_SMEM);

    round_weights<<<64, 256>>>(Wq, Wk, Wv, Wp);
    gemm_qkv_tc<<<dim3(NTOT / 128, 2, 3), 128, GEMM_SMEM>>>(x, bq, bk, bv);
    attn_kernel<<<dim3(H_, B_, 2), 256, ATTN_SMEM>>>(pbatch, pidx);
    gemm_proj_tc<<<dim3(NTOT / 128, 2), 128, GEMM_SMEM>>>(pinv, bp, out);
}